// round 10
// baseline (speedup 1.0000x reference)
#include <cuda_runtime.h>
#include <cuda_fp16.h>

#define B    4
#define CIN  3
#define COUT 16
#define H    256
#define W    256
#define K    5
#define PAD  2
#define NP   (H / 2)      // 128 pair-rows

// Intermediate as vertical row-pairs: g_midp[bo][p][col] = {y[2p][col], y[2p+1][col]}
__device__ __half2 g_midp[B * COUT * NP * W];   // 8 MB

// odd-parity pair {a.y, b.x}
__device__ __forceinline__ __half2 oddpair(__half2 a, __half2 b) {
    unsigned r = __byte_perm(*(unsigned*)&a, *(unsigned*)&b, 0x5432);
    return *(__half2*)&r;
}

// ---------------------------------------------------------------------------
// Dilation: tile 32x32, 4 rows/thread (2 even pairs), 8 o-channels per block
// (o split across grid.z for SM occupancy). fp32 accumulation over c.
// ---------------------------------------------------------------------------
#define DT_W 32
#define DT_H 32
#define DXR 18          // even pair rows: tile_y-2 .. tile_y+33
#define DXC (DT_W + 4)  // 36 cols
#define OCH 8           // channels per block

__global__ __launch_bounds__(256) void dilate_kernel(const float* __restrict__ x,
                                                     const float* __restrict__ wd) {
    __shared__ __half2 xs2[CIN][DXR][DXC];      // even row pairs {x[2p], x[2p+1]}
    __shared__ __half2 wsh[OCH * CIN * K * K];  // {w, w} for this block's 8 channels

    const int bz     = blockIdx.z;              // b*2 + chunk
    const int b      = bz >> 1;
    const int och    = (bz & 1) * OCH;
    const int tile_y = blockIdx.y * DT_H;
    const int tile_x = blockIdx.x * DT_W;
    const int tid    = threadIdx.y * 32 + threadIdx.x;

    // this chunk's weights are contiguous: wd[och*75 .. och*75+600)
    for (int i = tid; i < OCH * CIN * K * K; i += 256)
        wsh[i] = __float2half2_rn(wd[och * CIN * K * K + i]);

    // fill even pairs: pair k = rows {tile_y-2+2k, tile_y-1+2k}, clamped
    const int XN = CIN * DXR * DXC;
    for (int i = tid; i < XN; i += 256) {
        int c   = i / (DXR * DXC);
        int rem = i % (DXR * DXC);
        int k   = rem / DXC;
        int col = rem % DXC;
        int r0 = min(max(tile_y - 2 + 2 * k, 0), H - 1);
        int r1 = min(max(tile_y - 1 + 2 * k, 0), H - 1);
        int gj = min(max(tile_x + col - PAD, 0), W - 1);
        const float* xc = x + ((size_t)(b * CIN + c)) * H * W;
        xs2[c][k][col] = __floats2half2_rn(xc[r0 * W + gj], xc[r1 * W + gj]);
    }
    __syncthreads();

    const int tx = threadIdx.x;
    const int ty = threadIdx.y;
    const int gj = tile_x + tx;
    const int p0 = (tile_y >> 1) + ty * 2;      // global pair index of pair A

    const __half2 NEGINF2 = __half2half2(__ushort_as_half((unsigned short)0xFC00));

    float aA0[OCH], aA1[OCH], aB0[OCH], aB1[OCH];
#pragma unroll
    for (int o = 0; o < OCH; o++) { aA0[o] = aA1[o] = aB0[o] = aB1[o] = 0.0f; }

#pragma unroll
    for (int c = 0; c < CIN; c++) {
        __half2 mA[OCH], mB[OCH];
#pragma unroll
        for (int o = 0; o < OCH; o++) { mA[o] = NEGINF2; mB[o] = NEGINF2; }

#pragma unroll
        for (int dj = 0; dj < K; dj++) {
            __half2 E0 = xs2[c][ty * 2 + 0][tx + dj];
            __half2 E1 = xs2[c][ty * 2 + 1][tx + dj];
            __half2 E2 = xs2[c][ty * 2 + 2][tx + dj];
            __half2 E3 = xs2[c][ty * 2 + 3][tx + dj];
            __half2 O0 = oddpair(E0, E1);
            __half2 O1 = oddpair(E1, E2);
            __half2 O2 = oddpair(E2, E3);

#pragma unroll
            for (int o = 0; o < OCH; o++) {
                const __half2* w = &wsh[(o * CIN + c) * (K * K) + dj];
                __half2 w0 = w[0];
                __half2 w1 = w[K];
                __half2 w2 = w[2 * K];
                __half2 w3 = w[3 * K];
                __half2 w4 = w[4 * K];
                mA[o] = __hmax2(mA[o], __hadd2(E0, w0));
                mA[o] = __hmax2(mA[o], __hadd2(O0, w1));
                mA[o] = __hmax2(mA[o], __hadd2(E1, w2));
                mA[o] = __hmax2(mA[o], __hadd2(O1, w3));
                mA[o] = __hmax2(mA[o], __hadd2(E2, w4));
                mB[o] = __hmax2(mB[o], __hadd2(E1, w0));
                mB[o] = __hmax2(mB[o], __hadd2(O1, w1));
                mB[o] = __hmax2(mB[o], __hadd2(E2, w2));
                mB[o] = __hmax2(mB[o], __hadd2(O2, w3));
                mB[o] = __hmax2(mB[o], __hadd2(E3, w4));
            }
        }

#pragma unroll
        for (int o = 0; o < OCH; o++) {
            float2 fA = __half22float2(mA[o]);
            float2 fB = __half22float2(mB[o]);
            aA0[o] += fA.x; aA1[o] += fA.y;
            aB0[o] += fB.x; aB1[o] += fB.y;
        }
    }

#pragma unroll
    for (int o = 0; o < OCH; o++) {
        __half2* dst = &g_midp[((b * COUT + och + o) * NP + p0) * W + gj];
        dst[0] = __floats2half2_rn(aA0[o], aA1[o]);
        dst[W] = __floats2half2_rn(aB0[o], aB1[o]);
    }
}

// ---------------------------------------------------------------------------
// Erosion: out = min_t( y + (-w) ). Tile 64 cols x 64 rows, each thread does
// 8 rows x 2 columns (sequentially). Even pairs from smem; odd pairs via PRMT.
// ---------------------------------------------------------------------------
#define ER_TW 64
#define ER_TH 64
#define EP_R  34
#define EP_C  68

__global__ __launch_bounds__(256) void erode_kernel(const float* __restrict__ we_g,
                                                    float* __restrict__ out) {
    __shared__ __half2 ysp[EP_R][EP_C];
    __shared__ __half2 we2[K * K];          // {-w, -w}

    const int bo     = blockIdx.z;
    const int o      = bo % COUT;
    const int tile_y = blockIdx.y * ER_TH;
    const int tile_x = blockIdx.x * ER_TW;
    const int tx     = threadIdx.x;
    const int ty     = threadIdx.y;
    const int tid    = ty * 32 + tx;

    if (tid < K * K) {
        float w = we_g[o * K * K + tid];
        we2[tid] = __float2half2_rn(-w);
    }

    const __half2* yp = g_midp + (size_t)bo * NP * W;

    {
        const int gj0 = min(max(tile_x + tx - 2, 0), W - 1);        // cols 0..31
        const int gj1 = min(tile_x + tx + 30, W - 1);               // cols 32..63
        const int gj2 = min(tile_x + tx + 62, W - 1);               // cols 64..67 (tx<4)
        const int Pbase = (tile_y >> 1) - 1;
#pragma unroll
        for (int k = ty; k < EP_R; k += 8) {
            int Pr = Pbase + k;
            int P  = min(max(Pr, 0), NP - 1);
            bool lo = (Pr < 0), hi = (Pr > NP - 1);

            __half2 v0 = yp[P * W + gj0];
            if (lo) v0 = __half2half2(__low2half(v0));
            if (hi) v0 = __half2half2(__high2half(v0));
            ysp[k][tx] = v0;

            __half2 v1 = yp[P * W + gj1];
            if (lo) v1 = __half2half2(__low2half(v1));
            if (hi) v1 = __half2half2(__high2half(v1));
            ysp[k][32 + tx] = v1;

            if (tx < 4) {
                __half2 v2 = yp[P * W + gj2];
                if (lo) v2 = __half2half2(__low2half(v2));
                if (hi) v2 = __half2half2(__high2half(v2));
                ysp[k][64 + tx] = v2;
            }
        }
    }
    __syncthreads();

    const int pw = ty * 4;
    const __half2 INF2 = __half2half2(__ushort_as_half((unsigned short)0x7C00));

#pragma unroll
    for (int cc = 0; cc < 2; cc++) {
        const int lc = tx + cc * 32;

        __half2 m0 = INF2, m1 = INF2, m2 = INF2, m3 = INF2;

#pragma unroll
        for (int dj = 0; dj < K; dj++) {
            __half2 E0 = ysp[pw + 0][lc + dj];
            __half2 E1 = ysp[pw + 1][lc + dj];
            __half2 E2 = ysp[pw + 2][lc + dj];
            __half2 E3 = ysp[pw + 3][lc + dj];
            __half2 E4 = ysp[pw + 4][lc + dj];
            __half2 E5 = ysp[pw + 5][lc + dj];
            __half2 O0 = oddpair(E0, E1);
            __half2 O1 = oddpair(E1, E2);
            __half2 O2 = oddpair(E2, E3);
            __half2 O3 = oddpair(E3, E4);
            __half2 O4 = oddpair(E4, E5);

            __half2 w;
            w  = we2[0 * K + dj];
            m0 = __hmin2(m0, __hadd2(E0, w));
            m1 = __hmin2(m1, __hadd2(E1, w));
            m2 = __hmin2(m2, __hadd2(E2, w));
            m3 = __hmin2(m3, __hadd2(E3, w));
            w  = we2[1 * K + dj];
            m0 = __hmin2(m0, __hadd2(O0, w));
            m1 = __hmin2(m1, __hadd2(O1, w));
            m2 = __hmin2(m2, __hadd2(O2, w));
            m3 = __hmin2(m3, __hadd2(O3, w));
            w  = we2[2 * K + dj];
            m0 = __hmin2(m0, __hadd2(E1, w));
            m1 = __hmin2(m1, __hadd2(E2, w));
            m2 = __hmin2(m2, __hadd2(E3, w));
            m3 = __hmin2(m3, __hadd2(E4, w));
            w  = we2[3 * K + dj];
            m0 = __hmin2(m0, __hadd2(O1, w));
            m1 = __hmin2(m1, __hadd2(O2, w));
            m2 = __hmin2(m2, __hadd2(O3, w));
            m3 = __hmin2(m3, __hadd2(O4, w));
            w  = we2[4 * K + dj];
            m0 = __hmin2(m0, __hadd2(E2, w));
            m1 = __hmin2(m1, __hadd2(E3, w));
            m2 = __hmin2(m2, __hadd2(E4, w));
            m3 = __hmin2(m3, __hadd2(E5, w));
        }

        const int gi = tile_y + ty * 8;
        float* op = out + ((size_t)bo * H + gi) * W + tile_x + lc;
        float2 r;
        r = __half22float2(m0); op[0 * W] = r.x; op[1 * W] = r.y;
        r = __half22float2(m1); op[2 * W] = r.x; op[3 * W] = r.y;
        r = __half22float2(m2); op[4 * W] = r.x; op[5 * W] = r.y;
        r = __half22float2(m3); op[6 * W] = r.x; op[7 * W] = r.y;
    }
}

// ---------------------------------------------------------------------------
extern "C" void kernel_launch(void* const* d_in, const int* in_sizes, int n_in,
                              void* d_out, int out_size) {
    const float* x  = (const float*)d_in[0];
    const float* wd = (const float*)d_in[1];
    const float* we = (const float*)d_in[2];
    float*       out = (float*)d_out;

    dim3 bD(32, 8);
    dim3 gD(W / DT_W, H / DT_H, B * 2);      // 8 x 8 x 8 = 512 blocks
    dilate_kernel<<<gD, bD>>>(x, wd);

    dim3 bE(32, 8);
    dim3 gE(W / ER_TW, H / ER_TH, B * COUT); // 4 x 4 x 64 = 1024 blocks
    erode_kernel<<<gE, bE>>>(we, out);
}

// round 11
// speedup vs baseline: 1.1160x; 1.1160x over previous
#include <cuda_runtime.h>
#include <cuda_fp16.h>

#define B    4
#define CIN  3
#define COUT 16
#define H    256
#define W    256
#define K    5
#define PAD  2
#define NP   (H / 2)      // 128 pair-rows

// Intermediate as vertical row-pairs: g_midp[bo][p][col] = {y[2p][col], y[2p+1][col]}
__device__ __half2 g_midp[B * COUT * NP * W];   // 8 MB

// odd-parity pair {a.y, b.x}
__device__ __forceinline__ __half2 oddpair(__half2 a, __half2 b) {
    unsigned r = __byte_perm(*(unsigned*)&a, *(unsigned*)&b, 0x5432);
    return *(__half2*)&r;
}

// ---------------------------------------------------------------------------
// Dilation (R9 best): tile 32x32, 4 rows/thread (2 even pairs), all 16 o in
// one block as 2 chunks of 8. fp32 accumulation over c.
// ---------------------------------------------------------------------------
#define DT_W 32
#define DT_H 32
#define DXR 18          // even pair rows: tile_y-2 .. tile_y+33
#define DXC (DT_W + 4)  // 36 cols

__global__ __launch_bounds__(256) void dilate_kernel(const float* __restrict__ x,
                                                     const float* __restrict__ wd) {
    __shared__ __half2 xs2[CIN][DXR][DXC];      // even row pairs {x[2p], x[2p+1]}
    __shared__ __half2 wsh[COUT * CIN * K * K]; // {w, w} replicated

    const int b      = blockIdx.z;
    const int tile_y = blockIdx.y * DT_H;
    const int tile_x = blockIdx.x * DT_W;
    const int tid    = threadIdx.y * 32 + threadIdx.x;

    for (int i = tid; i < COUT * CIN * K * K; i += 256)
        wsh[i] = __float2half2_rn(wd[i]);

    // fill even pairs: pair k = rows {tile_y-2+2k, tile_y-1+2k}, clamped
    const int XN = CIN * DXR * DXC;
    for (int i = tid; i < XN; i += 256) {
        int c   = i / (DXR * DXC);
        int rem = i % (DXR * DXC);
        int k   = rem / DXC;
        int col = rem % DXC;
        int r0 = min(max(tile_y - 2 + 2 * k, 0), H - 1);
        int r1 = min(max(tile_y - 1 + 2 * k, 0), H - 1);
        int gj = min(max(tile_x + col - PAD, 0), W - 1);
        const float* xc = x + ((size_t)(b * CIN + c)) * H * W;
        xs2[c][k][col] = __floats2half2_rn(xc[r0 * W + gj], xc[r1 * W + gj]);
    }
    __syncthreads();

    const int tx = threadIdx.x;
    const int ty = threadIdx.y;
    const int gj = tile_x + tx;
    const int p0 = (tile_y >> 1) + ty * 2;      // global pair of output pair A

    const __half2 NEGINF2 = __half2half2(__ushort_as_half((unsigned short)0xFC00));

#pragma unroll
    for (int och = 0; och < COUT; och += 8) {
        float aA0[8], aA1[8], aB0[8], aB1[8];
#pragma unroll
        for (int o = 0; o < 8; o++) { aA0[o] = aA1[o] = aB0[o] = aB1[o] = 0.0f; }

#pragma unroll
        for (int c = 0; c < CIN; c++) {
            __half2 mA[8], mB[8];
#pragma unroll
            for (int o = 0; o < 8; o++) { mA[o] = NEGINF2; mB[o] = NEGINF2; }

#pragma unroll
            for (int dj = 0; dj < K; dj++) {
                __half2 E0 = xs2[c][ty * 2 + 0][tx + dj];
                __half2 E1 = xs2[c][ty * 2 + 1][tx + dj];
                __half2 E2 = xs2[c][ty * 2 + 2][tx + dj];
                __half2 E3 = xs2[c][ty * 2 + 3][tx + dj];
                __half2 O0 = oddpair(E0, E1);
                __half2 O1 = oddpair(E1, E2);
                __half2 O2 = oddpair(E2, E3);

#pragma unroll
                for (int o = 0; o < 8; o++) {
                    const __half2* w = &wsh[((och + o) * CIN + c) * (K * K) + dj];
                    __half2 w0 = w[0];
                    __half2 w1 = w[K];
                    __half2 w2 = w[2 * K];
                    __half2 w3 = w[3 * K];
                    __half2 w4 = w[4 * K];
                    // pair A (rows gr0, gr0+1)
                    mA[o] = __hmax2(mA[o], __hadd2(E0, w0));
                    mA[o] = __hmax2(mA[o], __hadd2(O0, w1));
                    mA[o] = __hmax2(mA[o], __hadd2(E1, w2));
                    mA[o] = __hmax2(mA[o], __hadd2(O1, w3));
                    mA[o] = __hmax2(mA[o], __hadd2(E2, w4));
                    // pair B (rows gr0+2, gr0+3)
                    mB[o] = __hmax2(mB[o], __hadd2(E1, w0));
                    mB[o] = __hmax2(mB[o], __hadd2(O1, w1));
                    mB[o] = __hmax2(mB[o], __hadd2(E2, w2));
                    mB[o] = __hmax2(mB[o], __hadd2(O2, w3));
                    mB[o] = __hmax2(mB[o], __hadd2(E3, w4));
                }
            }

#pragma unroll
            for (int o = 0; o < 8; o++) {
                float2 fA = __half22float2(mA[o]);
                float2 fB = __half22float2(mB[o]);
                aA0[o] += fA.x; aA1[o] += fA.y;
                aB0[o] += fB.x; aB1[o] += fB.y;
            }
        }

#pragma unroll
        for (int o = 0; o < 8; o++) {
            __half2* dst = &g_midp[((b * COUT + och + o) * NP + p0) * W + gj];
            dst[0] = __floats2half2_rn(aA0[o], aA1[o]);
            dst[W] = __floats2half2_rn(aB0[o], aB1[o]);
        }
    }
}

// ---------------------------------------------------------------------------
// Erosion (R10 best): tile 64x64, 8 rows x 2 cols per thread.
// ---------------------------------------------------------------------------
#define ER_TW 64
#define ER_TH 64
#define EP_R  34
#define EP_C  68

__global__ __launch_bounds__(256) void erode_kernel(const float* __restrict__ we_g,
                                                    float* __restrict__ out) {
    __shared__ __half2 ysp[EP_R][EP_C];
    __shared__ __half2 we2[K * K];          // {-w, -w}

    const int bo     = blockIdx.z;
    const int o      = bo % COUT;
    const int tile_y = blockIdx.y * ER_TH;
    const int tile_x = blockIdx.x * ER_TW;
    const int tx     = threadIdx.x;
    const int ty     = threadIdx.y;
    const int tid    = ty * 32 + tx;

    if (tid < K * K) {
        float w = we_g[o * K * K + tid];
        we2[tid] = __float2half2_rn(-w);
    }

    const __half2* yp = g_midp + (size_t)bo * NP * W;

    {
        const int gj0 = min(max(tile_x + tx - 2, 0), W - 1);        // cols 0..31
        const int gj1 = min(tile_x + tx + 30, W - 1);               // cols 32..63
        const int gj2 = min(tile_x + tx + 62, W - 1);               // cols 64..67 (tx<4)
        const int Pbase = (tile_y >> 1) - 1;
#pragma unroll
        for (int k = ty; k < EP_R; k += 8) {
            int Pr = Pbase + k;
            int P  = min(max(Pr, 0), NP - 1);
            bool lo = (Pr < 0), hi = (Pr > NP - 1);

            __half2 v0 = yp[P * W + gj0];
            if (lo) v0 = __half2half2(__low2half(v0));
            if (hi) v0 = __half2half2(__high2half(v0));
            ysp[k][tx] = v0;

            __half2 v1 = yp[P * W + gj1];
            if (lo) v1 = __half2half2(__low2half(v1));
            if (hi) v1 = __half2half2(__high2half(v1));
            ysp[k][32 + tx] = v1;

            if (tx < 4) {
                __half2 v2 = yp[P * W + gj2];
                if (lo) v2 = __half2half2(__low2half(v2));
                if (hi) v2 = __half2half2(__high2half(v2));
                ysp[k][64 + tx] = v2;
            }
        }
    }
    __syncthreads();

    const int pw = ty * 4;
    const __half2 INF2 = __half2half2(__ushort_as_half((unsigned short)0x7C00));

#pragma unroll
    for (int cc = 0; cc < 2; cc++) {
        const int lc = tx + cc * 32;

        __half2 m0 = INF2, m1 = INF2, m2 = INF2, m3 = INF2;

#pragma unroll
        for (int dj = 0; dj < K; dj++) {
            __half2 E0 = ysp[pw + 0][lc + dj];
            __half2 E1 = ysp[pw + 1][lc + dj];
            __half2 E2 = ysp[pw + 2][lc + dj];
            __half2 E3 = ysp[pw + 3][lc + dj];
            __half2 E4 = ysp[pw + 4][lc + dj];
            __half2 E5 = ysp[pw + 5][lc + dj];
            __half2 O0 = oddpair(E0, E1);
            __half2 O1 = oddpair(E1, E2);
            __half2 O2 = oddpair(E2, E3);
            __half2 O3 = oddpair(E3, E4);
            __half2 O4 = oddpair(E4, E5);

            __half2 w;
            w  = we2[0 * K + dj];
            m0 = __hmin2(m0, __hadd2(E0, w));
            m1 = __hmin2(m1, __hadd2(E1, w));
            m2 = __hmin2(m2, __hadd2(E2, w));
            m3 = __hmin2(m3, __hadd2(E3, w));
            w  = we2[1 * K + dj];
            m0 = __hmin2(m0, __hadd2(O0, w));
            m1 = __hmin2(m1, __hadd2(O1, w));
            m2 = __hmin2(m2, __hadd2(O2, w));
            m3 = __hmin2(m3, __hadd2(O3, w));
            w  = we2[2 * K + dj];
            m0 = __hmin2(m0, __hadd2(E1, w));
            m1 = __hmin2(m1, __hadd2(E2, w));
            m2 = __hmin2(m2, __hadd2(E3, w));
            m3 = __hmin2(m3, __hadd2(E4, w));
            w  = we2[3 * K + dj];
            m0 = __hmin2(m0, __hadd2(O1, w));
            m1 = __hmin2(m1, __hadd2(O2, w));
            m2 = __hmin2(m2, __hadd2(O3, w));
            m3 = __hmin2(m3, __hadd2(O4, w));
            w  = we2[4 * K + dj];
            m0 = __hmin2(m0, __hadd2(E2, w));
            m1 = __hmin2(m1, __hadd2(E3, w));
            m2 = __hmin2(m2, __hadd2(E4, w));
            m3 = __hmin2(m3, __hadd2(E5, w));
        }

        const int gi = tile_y + ty * 8;
        float* op = out + ((size_t)bo * H + gi) * W + tile_x + lc;
        float2 r;
        r = __half22float2(m0); op[0 * W] = r.x; op[1 * W] = r.y;
        r = __half22float2(m1); op[2 * W] = r.x; op[3 * W] = r.y;
        r = __half22float2(m2); op[4 * W] = r.x; op[5 * W] = r.y;
        r = __half22float2(m3); op[6 * W] = r.x; op[7 * W] = r.y;
    }
}

// ---------------------------------------------------------------------------
extern "C" void kernel_launch(void* const* d_in, const int* in_sizes, int n_in,
                              void* d_out, int out_size) {
    const float* x  = (const float*)d_in[0];
    const float* wd = (const float*)d_in[1];
    const float* we = (const float*)d_in[2];
    float*       out = (float*)d_out;

    dim3 bD(32, 8);
    dim3 gD(W / DT_W, H / DT_H, B);          // 8 x 8 x 4 = 256 blocks
    dilate_kernel<<<gD, bD>>>(x, wd);

    dim3 bE(32, 8);
    dim3 gE(W / ER_TW, H / ER_TH, B * COUT); // 4 x 4 x 64 = 1024 blocks
    erode_kernel<<<gE, bE>>>(we, out);
}